// round 3
// baseline (speedup 1.0000x reference)
#include <cuda_runtime.h>
#include <math.h>

// Shapes (fixed by the problem)
#define T 2048
#define B 32
#define H 1024
#define KSPLIT 32          // k-tiles of 32 for the v GEMM
#define NTG 128            // t-groups per b in k_scores (T/16)

// Scratch (allocation-free rule: __device__ globals)
__device__ float  g_vpart[KSPLIT][B][H];  // 4 MB split-k partials
__device__ float  g_v[B][H];              // 128 KB  v = hid @ W
__device__ float  g_scores[B][T];         // 256 KB  pre-softmax scores
__device__ float  g_pm[B][NTG];           // per-tgroup local max
__device__ float  g_ps[B][NTG];           // per-tgroup local sum of exp
__device__ float2 g_minv[B];              // (M, 1/S) per b

// ---------------------------------------------------------------------------
// K1: v_part[ks][b][h] = sum over k in [ks*32, ks*32+32) of hid[b,k]*W[k,h]
// grid: (hchunk=2, bgroup=2, ksplit=32) = 128 blocks x 128 threads
// Each thread: 4 h (float4), 16 b, 32 k. Deterministic (no atomics).
// ---------------------------------------------------------------------------
__global__ void __launch_bounds__(128) k_vpart(const float* __restrict__ hid,
                                               const float* __restrict__ W) {
    __shared__ float hid_s[16][32];
    const int tid   = threadIdx.x;          // 0..127
    const int h0    = blockIdx.x * 512 + tid * 4;
    const int bbase = blockIdx.y * 16;
    const int kbase = blockIdx.z * 32;

    for (int i = tid; i < 16 * 32; i += 128) {
        int bb = i >> 5, kk = i & 31;
        hid_s[bb][kk] = hid[(bbase + bb) * H + kbase + kk];
    }
    __syncthreads();

    float4 acc[16];
#pragma unroll
    for (int bb = 0; bb < 16; bb++) acc[bb] = make_float4(0.f, 0.f, 0.f, 0.f);

#pragma unroll 4
    for (int kk = 0; kk < 32; kk++) {
        float4 w = *reinterpret_cast<const float4*>(&W[(size_t)(kbase + kk) * H + h0]);
#pragma unroll
        for (int bb = 0; bb < 16; bb++) {
            float hv = hid_s[bb][kk];
            acc[bb].x += hv * w.x;
            acc[bb].y += hv * w.y;
            acc[bb].z += hv * w.z;
            acc[bb].w += hv * w.w;
        }
    }

#pragma unroll
    for (int bb = 0; bb < 16; bb++) {
        *reinterpret_cast<float4*>(&g_vpart[blockIdx.z][bbase + bb][h0]) = acc[bb];
    }
}

// ---------------------------------------------------------------------------
// K2: v[b][h] = sum over ksplit of v_part   (32768 elems; vpart sits in L2)
// ---------------------------------------------------------------------------
__global__ void __launch_bounds__(256) k_vreduce() {
    int idx = blockIdx.x * blockDim.x + threadIdx.x;
    const float* vp = &g_vpart[0][0][0];
    float* v = &g_v[0][0];
    if (idx < B * H) {
        float s = 0.f;
#pragma unroll
        for (int p = 0; p < KSPLIT; p++) s += vp[p * (B * H) + idx];
        v[idx] = s;
    }
}

// ---------------------------------------------------------------------------
// K3: scores[b][t] = enc[t,b,:] . v[b,:]
// One warp = one b x 16 t's, processed as 2 groups of 8 (acc[8] keeps regs
// under the 64-reg / 4-blocks-per-SM threshold -> single wave at 512 blocks).
// Also emits per-tgroup online-softmax partials (local max, local sum-exp).
// Streams the full 256 MB encoderOutput exactly once (__ldcs) -> HBM-bound.
// ---------------------------------------------------------------------------
__global__ void __launch_bounds__(256) k_scores(const float* __restrict__ enc) {
    const int warp = threadIdx.x >> 5;
    const int lane = threadIdx.x & 31;
    const int gw   = blockIdx.x * 8 + warp;     // 0..4095
    const int b    = gw & 31;
    const int tg   = gw >> 5;                   // 0..127
    const int tbase = tg * 16;

    // v[b] into registers: 8 float4 per lane (lane covers h = i*128 + lane*4)
    float4 vreg[8];
#pragma unroll
    for (int i = 0; i < 8; i++) {
        vreg[i] = *reinterpret_cast<const float4*>(&g_v[b][i * 128 + lane * 4]);
    }

    float m_run = 0.f, s_run = 0.f;

#pragma unroll
    for (int g = 0; g < 2; g++) {
        float acc[8];
#pragma unroll
        for (int r = 0; r < 8; r++) {
            const int t = tbase + g * 8 + r;
            const float4* e = reinterpret_cast<const float4*>(
                enc + ((size_t)t * B + b) * H) + lane;
            float4 a = make_float4(0.f, 0.f, 0.f, 0.f);
#pragma unroll
            for (int i = 0; i < 8; i++) {
                float4 ev = __ldcs(&e[i * 32]);
                a.x += ev.x * vreg[i].x;
                a.y += ev.y * vreg[i].y;
                a.z += ev.z * vreg[i].z;
                a.w += ev.w * vreg[i].w;
            }
            acc[r] = (a.x + a.y) + (a.z + a.w);
        }

        // Pipelined butterfly: 8 independent 5-stage chains; all lanes get sums.
#pragma unroll
        for (int off = 16; off > 0; off >>= 1) {
#pragma unroll
            for (int r = 0; r < 8; r++)
                acc[r] += __shfl_xor_sync(0xFFFFFFFFu, acc[r], off);
        }

        if (lane == 0) {
#pragma unroll
            for (int r = 0; r < 8; r++) g_scores[b][tbase + g * 8 + r] = acc[r];
        }

        // local softmax partial for this group of 8
        float mg = acc[0];
#pragma unroll
        for (int r = 1; r < 8; r++) mg = fmaxf(mg, acc[r]);
        float sg = 0.f;
#pragma unroll
        for (int r = 0; r < 8; r++) sg += __expf(acc[r] - mg);

        if (g == 0) { m_run = mg; s_run = sg; }
        else {
            float nm = fmaxf(m_run, mg);
            s_run = s_run * __expf(m_run - nm) + sg * __expf(mg - nm);
            m_run = nm;
        }
    }

    if (lane == 0) {
        g_pm[b][tg] = m_run;
        g_ps[b][tg] = s_run;
    }
}

// ---------------------------------------------------------------------------
// K4: merge per-tgroup (m,s) partials -> (M, 1/S) per b. One warp per b,
// single block of 1024 threads. Deterministic (fixed shfl order).
// ---------------------------------------------------------------------------
__global__ void __launch_bounds__(1024) k_smreduce() {
    const int warp = threadIdx.x >> 5;   // = b
    const int lane = threadIdx.x & 31;

    float m[4], s[4];
#pragma unroll
    for (int j = 0; j < 4; j++) {
        m[j] = g_pm[warp][lane + 32 * j];
        s[j] = g_ps[warp][lane + 32 * j];
    }
    float M = fmaxf(fmaxf(m[0], m[1]), fmaxf(m[2], m[3]));
#pragma unroll
    for (int off = 16; off > 0; off >>= 1)
        M = fmaxf(M, __shfl_xor_sync(0xFFFFFFFFu, M, off));

    float S = 0.f;
#pragma unroll
    for (int j = 0; j < 4; j++) S += s[j] * __expf(m[j] - M);
#pragma unroll
    for (int off = 16; off > 0; off >>= 1)
        S += __shfl_xor_sync(0xFFFFFFFFu, S, off);

    if (lane == 0) g_minv[warp] = make_float2(M, 1.f / S);
}

// ---------------------------------------------------------------------------
// K5: out[b,0,t] = exp(scores[b][t] - M[b]) * inv[b].  Fully parallel, float4.
// 64 blocks x 256 threads = 16384 threads, one float4 each.
// ---------------------------------------------------------------------------
__global__ void __launch_bounds__(256) k_finish(float* __restrict__ out) {
    const int idx = blockIdx.x * 256 + threadIdx.x;   // 0..16383
    const int b = idx >> 9;                           // T/4 = 512 float4 per b
    float2 mi = g_minv[b];
    float4 sc = reinterpret_cast<const float4*>(&g_scores[0][0])[idx];
    float4 o;
    o.x = __expf(sc.x - mi.x) * mi.y;
    o.y = __expf(sc.y - mi.x) * mi.y;
    o.z = __expf(sc.z - mi.x) * mi.y;
    o.w = __expf(sc.w - mi.x) * mi.y;
    reinterpret_cast<float4*>(out)[idx] = o;
}

// ---------------------------------------------------------------------------
// Inputs (metadata order): hidden [1,B,H], encoderOutput [T,B,H], W [H,H], b [H]
// Output: [B,1,T] float32.  Bias is constant in t -> cancels in softmax.
// ---------------------------------------------------------------------------
extern "C" void kernel_launch(void* const* d_in, const int* in_sizes, int n_in,
                              void* d_out, int out_size) {
    const float* hid = (const float*)d_in[0];
    const float* enc = (const float*)d_in[1];
    const float* W   = (const float*)d_in[2];
    (void)in_sizes; (void)n_in; (void)out_size;
    float* out = (float*)d_out;

    k_vpart<<<dim3(2, 2, KSPLIT), 128>>>(hid, W);
    k_vreduce<<<(B * H + 255) / 256, 256>>>();
    k_scores<<<512, 256>>>(enc);
    k_smreduce<<<1, 1024>>>();
    k_finish<<<64, 256>>>(out);
}

// round 4
// speedup vs baseline: 1.3179x; 1.3179x over previous
#include <cuda_runtime.h>
#include <math.h>

// Shapes (fixed by the problem)
#define T 2048
#define B 32
#define H 1024
#define KSPLIT 32          // k-tiles of 32 for the v GEMM

// Scratch (allocation-free rule: __device__ globals)
__device__ float g_vpart[KSPLIT][B][H];   // 4 MB split-k partials
__device__ float g_v[B][H];               // 128 KB  v = hid @ W
__device__ float g_scores[B][T];          // 256 KB  pre-softmax scores

// ---------------------------------------------------------------------------
// K1: v_part[ks][b][h] = sum over k in [ks*32, ks*32+32) of hid[b,k]*W[k,h]
// grid: (hchunk=2, bgroup=4, ksplit=32) = 256 blocks x 128 threads
// Each thread: 4 h (float4), 8 b, 32 k. Deterministic (no atomics).
// ---------------------------------------------------------------------------
__global__ void __launch_bounds__(128) k_vpart(const float* __restrict__ hid,
                                               const float* __restrict__ W) {
    __shared__ float hid_s[8][32];
    const int tid   = threadIdx.x;          // 0..127
    const int h0    = blockIdx.x * 512 + tid * 4;
    const int bbase = blockIdx.y * 8;
    const int kbase = blockIdx.z * 32;

    for (int i = tid; i < 8 * 32; i += 128) {
        int bb = i >> 5, kk = i & 31;
        hid_s[bb][kk] = hid[(bbase + bb) * H + kbase + kk];
    }
    __syncthreads();

    float4 acc[8];
#pragma unroll
    for (int bb = 0; bb < 8; bb++) acc[bb] = make_float4(0.f, 0.f, 0.f, 0.f);

#pragma unroll 4
    for (int kk = 0; kk < 32; kk++) {
        float4 w = *reinterpret_cast<const float4*>(&W[(size_t)(kbase + kk) * H + h0]);
#pragma unroll
        for (int bb = 0; bb < 8; bb++) {
            float hv = hid_s[bb][kk];
            acc[bb].x += hv * w.x;
            acc[bb].y += hv * w.y;
            acc[bb].z += hv * w.z;
            acc[bb].w += hv * w.w;
        }
    }

#pragma unroll
    for (int bb = 0; bb < 8; bb++) {
        *reinterpret_cast<float4*>(&g_vpart[blockIdx.z][bbase + bb][h0]) = acc[bb];
    }
}

// ---------------------------------------------------------------------------
// K2: v[b][h] = sum over ksplit of v_part   (32768 elems; vpart sits in L2)
// ---------------------------------------------------------------------------
__global__ void __launch_bounds__(256) k_vreduce() {
    int idx = blockIdx.x * blockDim.x + threadIdx.x;
    const float* vp = &g_vpart[0][0][0];
    float* v = &g_v[0][0];
    if (idx < B * H) {
        float s = 0.f;
#pragma unroll
        for (int p = 0; p < KSPLIT; p++) s += vp[p * (B * H) + idx];
        v[idx] = s;
    }
}

// ---------------------------------------------------------------------------
// K3: scores[b][t] = enc[t,b,:] . v[b,:]
// One warp owns one b and 16 consecutive t's. v[b] lives in SHARED memory
// (4 KB per warp, conflict-free LDS.128) instead of registers: cuts register
// pressure from ~75 to ~40 so 512 blocks fit in a single wave (5-6 CTA/SM).
// All 16 rows' loads are independent (max MLP); one pipelined butterfly at
// the end. enc streamed once with __ldcs (256 MB) -> HBM-bound.
// grid: 512 blocks x 256 threads (8 warps) = 4096 warps = 32 b x 128 t-groups
// ---------------------------------------------------------------------------
__global__ void __launch_bounds__(256) k_scores(const float* __restrict__ enc) {
    __shared__ float v_s[8][H];                 // 32 KB: one v row per warp
    const int warp = threadIdx.x >> 5;
    const int lane = threadIdx.x & 31;
    const int gw   = blockIdx.x * 8 + warp;     // 0..4095
    const int b    = gw & 31;
    const int tbase = (gw >> 5) * 16;

    // each warp stages its own v[b] (b's within a block are distinct: base+0..7)
#pragma unroll
    for (int i = 0; i < 8; i++) {
        *reinterpret_cast<float4*>(&v_s[warp][i * 128 + lane * 4]) =
            *reinterpret_cast<const float4*>(&g_v[b][i * 128 + lane * 4]);
    }
    __syncwarp();

    float acc[16];
#pragma unroll
    for (int tt = 0; tt < 16; tt++) {
        const int t = tbase + tt;
        const float4* e = reinterpret_cast<const float4*>(
            enc + ((size_t)t * B + b) * H) + lane;   // lane*4 floats in
        float4 a = make_float4(0.f, 0.f, 0.f, 0.f);
#pragma unroll
        for (int i = 0; i < 8; i++) {
            float4 ev = __ldcs(&e[i * 32]);          // h = i*128 + lane*4
            float4 vv = *reinterpret_cast<const float4*>(&v_s[warp][i * 128 + lane * 4]);
            a.x += ev.x * vv.x;
            a.y += ev.y * vv.y;
            a.z += ev.z * vv.z;
            a.w += ev.w * vv.w;
        }
        acc[tt] = (a.x + a.y) + (a.z + a.w);
    }

    // Pipelined multi-value butterfly: 16 independent 5-stage chains.
#pragma unroll
    for (int off = 16; off > 0; off >>= 1) {
#pragma unroll
        for (int i = 0; i < 16; i++)
            acc[i] += __shfl_xor_sync(0xFFFFFFFFu, acc[i], off);
    }

    if (lane == 0) {
#pragma unroll
        for (int i = 0; i < 16; i++) g_scores[b][tbase + i] = acc[i];
    }
}

// ---------------------------------------------------------------------------
// K4: out[b,0,t] = softmax over t of scores[b][t].  One block (1024 thr) per b.
// Warp-shuffle reductions; only 4 __syncthreads total. (R2 version, 5.2us)
// ---------------------------------------------------------------------------
__global__ void __launch_bounds__(1024) k_softmax(float* __restrict__ out) {
    __shared__ float red[32];
    __shared__ float bcast;
    const int b = blockIdx.x, tid = threadIdx.x;
    const int warp = tid >> 5, lane = tid & 31;
    const float* s = &g_scores[b][0];
    float* o = out + (size_t)b * T;

    float x0 = s[tid], x1 = s[tid + 1024];

    // --- max ---
    float m = fmaxf(x0, x1);
#pragma unroll
    for (int off = 16; off > 0; off >>= 1)
        m = fmaxf(m, __shfl_xor_sync(0xFFFFFFFFu, m, off));
    if (lane == 0) red[warp] = m;
    __syncthreads();
    if (warp == 0) {
        float mm = red[lane];
#pragma unroll
        for (int off = 16; off > 0; off >>= 1)
            mm = fmaxf(mm, __shfl_xor_sync(0xFFFFFFFFu, mm, off));
        if (lane == 0) bcast = mm;
    }
    __syncthreads();
    m = bcast;

    // --- exp + sum ---
    float e0 = __expf(x0 - m);
    float e1 = __expf(x1 - m);
    float sum = e0 + e1;
#pragma unroll
    for (int off = 16; off > 0; off >>= 1)
        sum += __shfl_xor_sync(0xFFFFFFFFu, sum, off);
    if (lane == 0) red[warp] = sum;
    __syncthreads();
    if (warp == 0) {
        float ss = red[lane];
#pragma unroll
        for (int off = 16; off > 0; off >>= 1)
            ss += __shfl_xor_sync(0xFFFFFFFFu, ss, off);
        if (lane == 0) bcast = 1.f / ss;
    }
    __syncthreads();
    float inv = bcast;

    o[tid] = e0 * inv;
    o[tid + 1024] = e1 * inv;
}

// ---------------------------------------------------------------------------
// Inputs (metadata order): hidden [1,B,H], encoderOutput [T,B,H], W [H,H], b [H]
// Output: [B,1,T] float32.  Bias is constant in t -> cancels in softmax.
// ---------------------------------------------------------------------------
extern "C" void kernel_launch(void* const* d_in, const int* in_sizes, int n_in,
                              void* d_out, int out_size) {
    const float* hid = (const float*)d_in[0];
    const float* enc = (const float*)d_in[1];
    const float* W   = (const float*)d_in[2];
    (void)in_sizes; (void)n_in; (void)out_size;
    float* out = (float*)d_out;

    k_vpart<<<dim3(2, 4, KSPLIT), 128>>>(hid, W);
    k_vreduce<<<(B * H + 255) / 256, 256>>>();
    k_scores<<<512, 256>>>(enc);
    k_softmax<<<B, 1024>>>(out);
}